// round 2
// baseline (speedup 1.0000x reference)
#include <cuda_runtime.h>

// CNNEmbedding: word[16384,32] int32, emb[512,128] f32, conv banks k=2..6 (16 filters each),
// pads {0,0,1,2,3}, max over positions, concat -> out[16384,80] f32.
//
// Strategy: only 512 vocab rows exist. Precompute T[v][f][pair] = dot(emb[v], W_k[f,:,j])
// for all 20 (k,j) tap pairs -> 640KB table. Then each word is pure gather + sliding-window
// ring accumulation + max. No per-word GEMM at all.

#define VOC 512
#define EMB 128
#define NF 16
#define NPAIR 20
#define LSEQ 32

__device__ float g_T[VOC * NF * NPAIR];  // [v][f][pair], pair-major innermost (80B stride, 16B aligned)

// ---------------------------------------------------------------------------
// Kernel 1: build table. grid=512 (one block per vocab entry), block=320 (16 f x 20 pairs)
// ---------------------------------------------------------------------------
__global__ void __launch_bounds__(320) build_table(
    const float* __restrict__ emb,
    const float* __restrict__ w2, const float* __restrict__ w3,
    const float* __restrict__ w4, const float* __restrict__ w5,
    const float* __restrict__ w6)
{
    __shared__ float semb[EMB];
    const int v = blockIdx.x;
    const int tid = threadIdx.x;
    if (tid < EMB) semb[tid] = emb[v * EMB + tid];
    __syncthreads();

    const int f  = tid / NPAIR;
    const int pr = tid % NPAIR;

    int k, j;
    const float* w;
    if (pr < 2)       { k = 2; j = pr;      w = w2; }
    else if (pr < 5)  { k = 3; j = pr - 2;  w = w3; }
    else if (pr < 9)  { k = 4; j = pr - 5;  w = w4; }
    else if (pr < 14) { k = 5; j = pr - 9;  w = w5; }
    else              { k = 6; j = pr - 14; w = w6; }

    // w layout [O=16, I=128, K=k] row-major: w[f, e, j] = w[f*128*k + e*k + j]
    const float* wrow = w + f * EMB * k + j;
    float s = 0.f;
#pragma unroll 16
    for (int e = 0; e < EMB; ++e)
        s = fmaf(semb[e], wrow[e * k], s);

    g_T[(v * NF + f) * NPAIR + pr] = s;
}

// ---------------------------------------------------------------------------
// Kernel 2: per-word gather + sliding-window max.
// block = 256 threads = 16 words x 16 filters. grid = 16384/16 = 1024.
// Thread (word w, filter f) runs all 5 kernel sizes with 20 ring accumulators.
// ---------------------------------------------------------------------------
__global__ void __launch_bounds__(256) cnn_max(
    const int* __restrict__ word,
    const float* __restrict__ b2, const float* __restrict__ b3,
    const float* __restrict__ b4, const float* __restrict__ b5,
    const float* __restrict__ b6,
    float* __restrict__ out)
{
    __shared__ int sidx[16 * LSEQ];
    const int tid = threadIdx.x;

    // Stage 16 words' indices (512 ints)
    sidx[tid]       = word[blockIdx.x * 512 + tid];
    sidx[tid + 256] = word[blockIdx.x * 512 + 256 + tid];
    __syncthreads();

    const int wl = tid >> 4;     // word-in-block 0..15
    const int f  = tid & 15;     // filter 0..15
    const int* midx = &sidx[wl * LSEQ];

    float acc[NPAIR];
#pragma unroll
    for (int i = 0; i < NPAIR; ++i) acc[i] = 0.f;
    float mx[5];
#pragma unroll
    for (int i = 0; i < 5; ++i) mx[i] = -3.402823466e38f;

    // Per-kernel constants (compile-time after unroll)
    const int KK[5]   = {2, 3, 4, 5, 6};
    const int PP[5]   = {0, 0, 1, 2, 3};
    const int BASE[5] = {0, 2, 5, 9, 14};   // both acc-slot base and vals-pair base

    // Walk positions -3..34: covers all padded windows (max pad = 3).
    // Out-of-range / unk positions contribute zero columns (matches reference padding/unk).
#pragma unroll
    for (int pos = -3; pos <= 34; ++pos) {
        float vals[NPAIR];
#pragma unroll
        for (int u = 0; u < NPAIR; ++u) vals[u] = 0.f;

        if (pos >= 0 && pos < LSEQ) {
            const int v = midx[pos];
            if (v >= 0) {
                const float4* p = reinterpret_cast<const float4*>(
                    g_T + (unsigned)((v << 4) + f) * NPAIR);
                float4 a;
                a = p[0]; vals[0]  = a.x; vals[1]  = a.y; vals[2]  = a.z; vals[3]  = a.w;
                a = p[1]; vals[4]  = a.x; vals[5]  = a.y; vals[6]  = a.z; vals[7]  = a.w;
                a = p[2]; vals[8]  = a.x; vals[9]  = a.y; vals[10] = a.z; vals[11] = a.w;
                a = p[3]; vals[12] = a.x; vals[13] = a.y; vals[14] = a.z; vals[15] = a.w;
                a = p[4]; vals[16] = a.x; vals[17] = a.y; vals[18] = a.z; vals[19] = a.w;
            }
        }

#pragma unroll
        for (int i = 0; i < 5; ++i) {
            const int k = KK[i], p = PP[i], ab = BASE[i];
            const int lout = LSEQ + 2 * p - k + 1;
            const int q = pos + p;            // padded-sequence position
#pragma unroll
            for (int j = 0; j < 6; ++j) {     // fixed bound; guard folds at compile time
                if (j < k) {
                    const int t = q - j;      // output index this tap feeds
                    if (t >= 0 && t < lout)
                        acc[ab + (t % k)] += vals[ab + j];
                }
            }
            const int tc = q - (k - 1);       // output completed at this position
            if (tc >= 0 && tc < lout) {
                const int s = ab + (tc % k);
                mx[i] = fmaxf(mx[i], acc[s]);
                acc[s] = 0.f;
            }
        }
    }

    const float bias[5] = {b2[f], b3[f], b4[f], b5[f], b6[f]};
    float* o = out + (blockIdx.x * 16 + wl) * 80;
#pragma unroll
    for (int i = 0; i < 5; ++i)
        o[i * 16 + f] = mx[i] + bias[i];
}

// ---------------------------------------------------------------------------
extern "C" void kernel_launch(void* const* d_in, const int* in_sizes, int n_in,
                              void* d_out, int out_size)
{
    const int*   word = (const int*)  d_in[0];
    const float* emb  = (const float*)d_in[1];
    const float* w2   = (const float*)d_in[2];
    const float* b2   = (const float*)d_in[3];
    const float* w3   = (const float*)d_in[4];
    const float* b3   = (const float*)d_in[5];
    const float* w4   = (const float*)d_in[6];
    const float* b4   = (const float*)d_in[7];
    const float* w5   = (const float*)d_in[8];
    const float* b5   = (const float*)d_in[9];
    const float* w6   = (const float*)d_in[10];
    const float* b6   = (const float*)d_in[11];
    float* out = (float*)d_out;

    build_table<<<VOC, 320>>>(emb, w2, w3, w4, w5, w6);
    cnn_max<<<1024, 256>>>(word, b2, b3, b4, b5, b6, out);
}

// round 3
// speedup vs baseline: 1.5610x; 1.5610x over previous
#include <cuda_runtime.h>
#include <cuda_fp16.h>

// CNNEmbedding via vocab-factorized table, fp16 edition.
// T[v][f][pair] = dot(emb[v], W_k[f,:,j]) for the 20 (k,j) taps, stored fp16,
// row padded 20->24 halves (48B stride) so each thread gathers 40B in 3 loads.
// cnn_max then does gather + sliding-window ring accumulation (fp32) + max.

#define VOC 512
#define EMB 128
#define NF 16
#define NPAIR 20
#define ROWH 24          // padded halves per (v,f) row -> 48B stride
#define LSEQ 32
#define VT 8             // vocab entries per build block

__device__ __align__(16) __half g_Th[VOC * NF * ROWH];   // 384 KB

// ---------------------------------------------------------------------------
// Kernel 1: build table. grid = VOC/VT = 64, block = 320 (16 f x 20 pairs).
// Each block handles VT vocab entries; emb tile staged in smem; each weight
// element is loaded once per block and reused VT times (L1-register reuse).
// ---------------------------------------------------------------------------
__global__ void __launch_bounds__(320) build_table(
    const float* __restrict__ emb,
    const float* __restrict__ w2, const float* __restrict__ w3,
    const float* __restrict__ w4, const float* __restrict__ w5,
    const float* __restrict__ w6)
{
    __shared__ float semb[VT][EMB];
    const int v0  = blockIdx.x * VT;
    const int tid = threadIdx.x;

    for (int i = tid; i < VT * EMB; i += 320)
        ((float*)semb)[i] = emb[v0 * EMB + i];
    __syncthreads();

    const int f  = tid / NPAIR;
    const int pr = tid % NPAIR;

    int k, j;
    const float* w;
    if (pr < 2)       { k = 2; j = pr;      w = w2; }
    else if (pr < 5)  { k = 3; j = pr - 2;  w = w3; }
    else if (pr < 9)  { k = 4; j = pr - 5;  w = w4; }
    else if (pr < 14) { k = 5; j = pr - 9;  w = w5; }
    else              { k = 6; j = pr - 14; w = w6; }

    // w layout [O=16, I=128, K=k]: w[f, e, j] = w[f*128*k + e*k + j]
    const float* wrow = w + f * EMB * k + j;

    float acc[VT];
#pragma unroll
    for (int t = 0; t < VT; ++t) acc[t] = 0.f;

#pragma unroll 4
    for (int e = 0; e < EMB; ++e) {
        const float we = wrow[e * k];
#pragma unroll
        for (int t = 0; t < VT; ++t)
            acc[t] = fmaf(semb[t][e], we, acc[t]);   // smem broadcast reads
    }

#pragma unroll
    for (int t = 0; t < VT; ++t)
        g_Th[((v0 + t) * NF + f) * ROWH + pr] = __float2half(acc[t]);
}

// ---------------------------------------------------------------------------
// Kernel 2: per-word gather + sliding-window max.
// block = 256 = 16 words x 16 filters; grid = 1024.
// ---------------------------------------------------------------------------
__global__ void __launch_bounds__(256) cnn_max(
    const int* __restrict__ word,
    const float* __restrict__ b2, const float* __restrict__ b3,
    const float* __restrict__ b4, const float* __restrict__ b5,
    const float* __restrict__ b6,
    float* __restrict__ out)
{
    __shared__ int sidx[16 * LSEQ];
    const int tid = threadIdx.x;

    sidx[tid]       = word[blockIdx.x * 512 + tid];
    sidx[tid + 256] = word[blockIdx.x * 512 + 256 + tid];
    __syncthreads();

    const int wl = tid >> 4;
    const int f  = tid & 15;
    const int* midx = &sidx[wl * LSEQ];

    float acc[NPAIR];
#pragma unroll
    for (int i = 0; i < NPAIR; ++i) acc[i] = 0.f;
    float mx[5];
#pragma unroll
    for (int i = 0; i < 5; ++i) mx[i] = -3.402823466e38f;

    const int KK[5]   = {2, 3, 4, 5, 6};
    const int PP[5]   = {0, 0, 1, 2, 3};
    const int BASE[5] = {0, 2, 5, 9, 14};

#pragma unroll
    for (int pos = -3; pos <= 34; ++pos) {
        float vals[NPAIR];
#pragma unroll
        for (int u = 0; u < NPAIR; ++u) vals[u] = 0.f;

        if (pos >= 0 && pos < LSEQ) {
            const int v = midx[pos];
            if (v >= 0) {
                const __half* rp = g_Th + (unsigned)((v << 4) + f) * ROWH;
                const uint4 a = *reinterpret_cast<const uint4*>(rp);        // pairs 0..7
                const uint4 b = *reinterpret_cast<const uint4*>(rp + 8);    // pairs 8..15
                const uint2 c = *reinterpret_cast<const uint2*>(rp + 16);   // pairs 16..19
                const unsigned pk[10] = {a.x, a.y, a.z, a.w, b.x, b.y, b.z, b.w, c.x, c.y};
#pragma unroll
                for (int i = 0; i < 10; ++i) {
                    const float2 f2 = __half22float2(*reinterpret_cast<const __half2*>(&pk[i]));
                    vals[2 * i]     = f2.x;
                    vals[2 * i + 1] = f2.y;
                }
            }
        }

#pragma unroll
        for (int i = 0; i < 5; ++i) {
            const int k = KK[i], p = PP[i], ab = BASE[i];
            const int lout = LSEQ + 2 * p - k + 1;
            const int q = pos + p;
#pragma unroll
            for (int j = 0; j < 6; ++j) {
                if (j < k) {
                    const int t = q - j;
                    if (t >= 0 && t < lout)
                        acc[ab + (t % k)] += vals[ab + j];
                }
            }
            const int tc = q - (k - 1);
            if (tc >= 0 && tc < lout) {
                const int s = ab + (tc % k);
                mx[i] = fmaxf(mx[i], acc[s]);
                acc[s] = 0.f;
            }
        }
    }

    const float bias[5] = {b2[f], b3[f], b4[f], b5[f], b6[f]};
    float* o = out + (blockIdx.x * 16 + wl) * 80;
#pragma unroll
    for (int i = 0; i < 5; ++i)
        o[i * 16 + f] = mx[i] + bias[i];
}

// ---------------------------------------------------------------------------
extern "C" void kernel_launch(void* const* d_in, const int* in_sizes, int n_in,
                              void* d_out, int out_size)
{
    const int*   word = (const int*)  d_in[0];
    const float* emb  = (const float*)d_in[1];
    const float* w2   = (const float*)d_in[2];
    const float* b2   = (const float*)d_in[3];
    const float* w3   = (const float*)d_in[4];
    const float* b3   = (const float*)d_in[5];
    const float* w4   = (const float*)d_in[6];
    const float* b4   = (const float*)d_in[7];
    const float* w5   = (const float*)d_in[8];
    const float* b5   = (const float*)d_in[9];
    const float* w6   = (const float*)d_in[10];
    const float* b6   = (const float*)d_in[11];
    float* out = (float*)d_out;

    build_table<<<VOC / VT, 320>>>(emb, w2, w3, w4, w5, w6);
    cnn_max<<<1024, 256>>>(word, b2, b3, b4, b5, b6, out);
}

// round 4
// speedup vs baseline: 1.6259x; 1.0416x over previous
#include <cuda_runtime.h>
#include <cuda_fp16.h>

// CNNEmbedding via vocab-factorized fp16 table + fp16 ring accumulation.
// T[v][f][pair] = dot(emb[v], W_k[f,:,j]) for 20 (k,j) taps, fp16, row padded to
// 24 halves (48B). cnn_max gathers rows and runs fully-unrolled sliding-window
// ring accumulation entirely in fp16 (HADD2/HMNMX with lane selectors; no F2F
// in the hot loop), max in fp16 (exact), final bias add in fp32.

#define VOC 512
#define EMB 128
#define NF 16
#define NPAIR 20
#define ROWH 24
#define LSEQ 32
#define VT 4

__device__ __align__(16) __half g_Th[VOC * NF * ROWH];   // 384 KB

// ---------------------------------------------------------------------------
// Kernel 1: build table. grid = VOC/VT = 128, block = 320 (16 f x 20 pairs).
// ---------------------------------------------------------------------------
__global__ void __launch_bounds__(320) build_table(
    const float* __restrict__ emb,
    const float* __restrict__ w2, const float* __restrict__ w3,
    const float* __restrict__ w4, const float* __restrict__ w5,
    const float* __restrict__ w6)
{
    __shared__ float semb[VT][EMB];
    const int v0  = blockIdx.x * VT;
    const int tid = threadIdx.x;

    for (int i = tid; i < VT * EMB; i += 320)
        ((float*)semb)[i] = emb[v0 * EMB + i];
    __syncthreads();

    const int f  = tid / NPAIR;
    const int pr = tid % NPAIR;

    int k, j;
    const float* w;
    if (pr < 2)       { k = 2; j = pr;      w = w2; }
    else if (pr < 5)  { k = 3; j = pr - 2;  w = w3; }
    else if (pr < 9)  { k = 4; j = pr - 5;  w = w4; }
    else if (pr < 14) { k = 5; j = pr - 9;  w = w5; }
    else              { k = 6; j = pr - 14; w = w6; }

    // w layout [O=16, I=128, K=k]: w[f, e, j] = w[f*128*k + e*k + j]
    const float* wrow = w + f * EMB * k + j;

    float acc[VT];
#pragma unroll
    for (int t = 0; t < VT; ++t) acc[t] = 0.f;

#pragma unroll 4
    for (int e = 0; e < EMB; ++e) {
        const float we = wrow[e * k];
#pragma unroll
        for (int t = 0; t < VT; ++t)
            acc[t] = fmaf(semb[t][e], we, acc[t]);
    }

#pragma unroll
    for (int t = 0; t < VT; ++t)
        g_Th[((v0 + t) * NF + f) * ROWH + pr] = __float2half(acc[t]);
}

// ---------------------------------------------------------------------------
// Kernel 2: per-word gather + fp16 sliding-window max.
// block = 256 = 16 words x 16 filters; grid = 1024.
// ---------------------------------------------------------------------------
__device__ __forceinline__ __half hget(const __half2* vh, int i) {
    // i is compile-time under full unroll -> folds into HADD2 lane selector
    return (i & 1) ? __high2half(vh[i >> 1]) : __low2half(vh[i >> 1]);
}

__global__ void __launch_bounds__(256) cnn_max(
    const int* __restrict__ word,
    const float* __restrict__ b2, const float* __restrict__ b3,
    const float* __restrict__ b4, const float* __restrict__ b5,
    const float* __restrict__ b6,
    float* __restrict__ out)
{
    __shared__ int sidx[16 * LSEQ];
    const int tid = threadIdx.x;

    sidx[tid]       = word[blockIdx.x * 512 + tid];
    sidx[tid + 256] = word[blockIdx.x * 512 + 256 + tid];
    __syncthreads();

    const int wl = tid >> 4;
    const int f  = tid & 15;
    const int* midx = &sidx[wl * LSEQ];

    const __half HZERO = __ushort_as_half((unsigned short)0);
    const __half HNEG  = __ushort_as_half((unsigned short)0xFBFF);  // -65504

    __half acc[NPAIR];
#pragma unroll
    for (int i = 0; i < NPAIR; ++i) acc[i] = HZERO;
    __half mx[5];
#pragma unroll
    for (int i = 0; i < 5; ++i) mx[i] = HNEG;

    const int KK[5]   = {2, 3, 4, 5, 6};
    const int PP[5]   = {0, 0, 1, 2, 3};
    const int BASE[5] = {0, 2, 5, 9, 14};

    // Main loop: real positions only. (pos<0 provably contributes nothing:
    // vals are zero and no window can complete before pos >= k-1-p >= 1.)
#pragma unroll
    for (int pos = 0; pos < LSEQ; ++pos) {
        __half2 vh[10];
#pragma unroll
        for (int u = 0; u < 10; ++u) vh[u] = __half2half2(HZERO);

        const int v = midx[pos];
        if (v >= 0) {
            const __half* rp = g_Th + (unsigned)((v << 4) + f) * ROWH;
            const uint4 a = *reinterpret_cast<const uint4*>(rp);       // pairs 0..7
            const uint4 b = *reinterpret_cast<const uint4*>(rp + 8);   // pairs 8..15
            const uint2 c = *reinterpret_cast<const uint2*>(rp + 16);  // pairs 16..19
            vh[0] = *reinterpret_cast<const __half2*>(&a.x);
            vh[1] = *reinterpret_cast<const __half2*>(&a.y);
            vh[2] = *reinterpret_cast<const __half2*>(&a.z);
            vh[3] = *reinterpret_cast<const __half2*>(&a.w);
            vh[4] = *reinterpret_cast<const __half2*>(&b.x);
            vh[5] = *reinterpret_cast<const __half2*>(&b.y);
            vh[6] = *reinterpret_cast<const __half2*>(&b.z);
            vh[7] = *reinterpret_cast<const __half2*>(&b.w);
            vh[8] = *reinterpret_cast<const __half2*>(&c.x);
            vh[9] = *reinterpret_cast<const __half2*>(&c.y);
        }

#pragma unroll
        for (int i = 0; i < 5; ++i) {
            const int k = KK[i], p = PP[i], ab = BASE[i];
            const int lout = LSEQ + 2 * p - k + 1;
            const int q = pos + p;
#pragma unroll
            for (int j = 0; j < 6; ++j) {
                if (j < k) {
                    const int t = q - j;
                    if (t >= 0 && t < lout)
                        acc[ab + (t % k)] = __hadd(acc[ab + (t % k)], hget(vh, ab + j));
                }
            }
            const int tc = q - (k - 1);
            if (tc >= 0 && tc < lout) {
                const int s = ab + (tc % k);
                mx[i] = __hmax(mx[i], acc[s]);
                acc[s] = HZERO;
            }
        }
    }

    // Epilogue: positions 32..34 have zero vals; only completions remain.
#pragma unroll
    for (int pos = LSEQ; pos <= LSEQ + 2; ++pos) {
#pragma unroll
        for (int i = 0; i < 5; ++i) {
            const int k = KK[i], p = PP[i], ab = BASE[i];
            const int lout = LSEQ + 2 * p - k + 1;
            const int tc = pos + p - (k - 1);
            if (tc >= 0 && tc < lout)
                mx[i] = __hmax(mx[i], acc[ab + (tc % k)]);
        }
    }

    const float bias[5] = {b2[f], b3[f], b4[f], b5[f], b6[f]};
    float* o = out + (blockIdx.x * 16 + wl) * 80;
#pragma unroll
    for (int i = 0; i < 5; ++i)
        o[i * 16 + f] = __half2float(mx[i]) + bias[i];
}

// ---------------------------------------------------------------------------
extern "C" void kernel_launch(void* const* d_in, const int* in_sizes, int n_in,
                              void* d_out, int out_size)
{
    const int*   word = (const int*)  d_in[0];
    const float* emb  = (const float*)d_in[1];
    const float* w2   = (const float*)d_in[2];
    const float* b2   = (const float*)d_in[3];
    const float* w3   = (const float*)d_in[4];
    const float* b3   = (const float*)d_in[5];
    const float* w4   = (const float*)d_in[6];
    const float* b4   = (const float*)d_in[7];
    const float* w5   = (const float*)d_in[8];
    const float* b5   = (const float*)d_in[9];
    const float* w6   = (const float*)d_in[10];
    const float* b6   = (const float*)d_in[11];
    float* out = (float*)d_out;

    build_table<<<VOC / VT, 320>>>(emb, w2, w3, w4, w5, w6);
    cnn_max<<<1024, 256>>>(word, b2, b3, b4, b5, b6, out);
}

// round 5
// speedup vs baseline: 1.6700x; 1.0271x over previous
#include <cuda_runtime.h>
#include <cuda_fp16.h>

// CNNEmbedding via vocab-factorized fp16 table + fp16 ring accumulation.
// Table layout: T[v][chunk][filter] with 16B chunks -> per-warp gathers are
// contiguous 256B per load instruction (no L1 line amplification).
// Row v=VOC is an all-zero row used for unk chars (branch-free gather).

#define VOC 512
#define EMB 128
#define NF 16
#define NPAIR 20
#define LSEQ 32
#define VT 4

// Per-v block: 3 chunks x 16 filters x 16B = 768B = 384 halves.
// (VOC+1) rows: last row stays zero (device globals are zero-initialized,
// build_table never writes it) -> serves unk characters.
__device__ __align__(16) __half g_Th[(VOC + 1) * 384];

// ---------------------------------------------------------------------------
// Kernel 1: build table. grid = VOC/VT = 128, block = 320 (16 f x 20 taps).
// ---------------------------------------------------------------------------
__global__ void __launch_bounds__(320) build_table(
    const float* __restrict__ emb,
    const float* __restrict__ w2, const float* __restrict__ w3,
    const float* __restrict__ w4, const float* __restrict__ w5,
    const float* __restrict__ w6)
{
    __shared__ float semb[VT][EMB];
    const int v0  = blockIdx.x * VT;
    const int tid = threadIdx.x;

    for (int i = tid; i < VT * EMB; i += 320)
        ((float*)semb)[i] = emb[v0 * EMB + i];
    __syncthreads();

    const int f  = tid / NPAIR;
    const int pr = tid % NPAIR;

    int k, j;
    const float* w;
    if (pr < 2)       { k = 2; j = pr;      w = w2; }
    else if (pr < 5)  { k = 3; j = pr - 2;  w = w3; }
    else if (pr < 9)  { k = 4; j = pr - 5;  w = w4; }
    else if (pr < 14) { k = 5; j = pr - 9;  w = w5; }
    else              { k = 6; j = pr - 14; w = w6; }

    // w layout [O=16, I=128, K=k]: w[f, e, j] = w[f*128*k + e*k + j]
    const float* wrow = w + f * EMB * k + j;

    float acc[VT];
#pragma unroll
    for (int t = 0; t < VT; ++t) acc[t] = 0.f;

#pragma unroll 4
    for (int e = 0; e < EMB; ++e) {
        const float we = wrow[e * k];
#pragma unroll
        for (int t = 0; t < VT; ++t)
            acc[t] = fmaf(semb[t][e], we, acc[t]);
    }

    // chunk-transposed store: tap pr -> chunk c = pr/8, half h = pr%8
    const int c = pr >> 3;
    const int h = pr & 7;
#pragma unroll
    for (int t = 0; t < VT; ++t)
        g_Th[(v0 + t) * 384 + c * 128 + f * 8 + h] = __float2half(acc[t]);
}

// ---------------------------------------------------------------------------
// Kernel 2: per-word gather + fp16 sliding-window max.
// block = 256 = 16 words x 16 filters; grid = 1024. Straight-line inner loop:
// no branches, unconditional gathers (unk -> zero row).
// ---------------------------------------------------------------------------
__device__ __forceinline__ __half hget(const __half2* vh, int i) {
    return (i & 1) ? __high2half(vh[i >> 1]) : __low2half(vh[i >> 1]);
}

__global__ void __launch_bounds__(256) cnn_max(
    const int* __restrict__ word,
    const float* __restrict__ b2, const float* __restrict__ b3,
    const float* __restrict__ b4, const float* __restrict__ b5,
    const float* __restrict__ b6,
    float* __restrict__ out)
{
    __shared__ int sidx[16 * LSEQ];
    const int tid = threadIdx.x;

    sidx[tid]       = word[blockIdx.x * 512 + tid];
    sidx[tid + 256] = word[blockIdx.x * 512 + 256 + tid];
    __syncthreads();

    const int wl = tid >> 4;
    const int f  = tid & 15;
    const int* midx = &sidx[wl * LSEQ];

    // bias loads early, overlap with gather loop
    const float bias[5] = {b2[f], b3[f], b4[f], b5[f], b6[f]};

    const __half HZERO = __ushort_as_half((unsigned short)0);
    const __half HNEG  = __ushort_as_half((unsigned short)0xFBFF);  // -65504

    __half acc[NPAIR];
#pragma unroll
    for (int i = 0; i < NPAIR; ++i) acc[i] = HZERO;
    __half mx[5];
#pragma unroll
    for (int i = 0; i < 5; ++i) mx[i] = HNEG;

    const int KK[5]   = {2, 3, 4, 5, 6};
    const int PP[5]   = {0, 0, 1, 2, 3};
    const int BASE[5] = {0, 2, 5, 9, 14};

    const uint4* __restrict__ g4 = reinterpret_cast<const uint4*>(g_Th);

#pragma unroll
    for (int pos = 0; pos < LSEQ; ++pos) {
        int v = midx[pos];
        v = (v < 0) ? VOC : v;                 // unk -> zero row (SEL, no branch)
        const uint4* p = g4 + v * 48 + f;      // [v][chunk][filter] layout
        const uint4 a = p[0];                  // taps 0..7
        const uint4 b = p[16];                 // taps 8..15
        const uint4 c = p[32];                 // taps 16..19 (+pad)

        __half2 vh[10];
        vh[0] = *reinterpret_cast<const __half2*>(&a.x);
        vh[1] = *reinterpret_cast<const __half2*>(&a.y);
        vh[2] = *reinterpret_cast<const __half2*>(&a.z);
        vh[3] = *reinterpret_cast<const __half2*>(&a.w);
        vh[4] = *reinterpret_cast<const __half2*>(&b.x);
        vh[5] = *reinterpret_cast<const __half2*>(&b.y);
        vh[6] = *reinterpret_cast<const __half2*>(&b.z);
        vh[7] = *reinterpret_cast<const __half2*>(&b.w);
        vh[8] = *reinterpret_cast<const __half2*>(&c.x);
        vh[9] = *reinterpret_cast<const __half2*>(&c.y);

#pragma unroll
        for (int i = 0; i < 5; ++i) {
            const int k = KK[i], p_ = PP[i], ab = BASE[i];
            const int lout = LSEQ + 2 * p_ - k + 1;
            const int q = pos + p_;
#pragma unroll
            for (int j = 0; j < 6; ++j) {
                if (j < k) {
                    const int t = q - j;
                    if (t >= 0 && t < lout)
                        acc[ab + (t % k)] = __hadd(acc[ab + (t % k)], hget(vh, ab + j));
                }
            }
            const int tc = q - (k - 1);
            if (tc >= 0 && tc < lout) {
                const int s = ab + (tc % k);
                mx[i] = __hmax(mx[i], acc[s]);
                acc[s] = HZERO;
            }
        }
    }

    // Epilogue: positions 32..34 contribute zero taps; only completions remain.
#pragma unroll
    for (int pos = LSEQ; pos <= LSEQ + 2; ++pos) {
#pragma unroll
        for (int i = 0; i < 5; ++i) {
            const int k = KK[i], p_ = PP[i], ab = BASE[i];
            const int lout = LSEQ + 2 * p_ - k + 1;
            const int tc = pos + p_ - (k - 1);
            if (tc >= 0 && tc < lout)
                mx[i] = __hmax(mx[i], acc[ab + (tc % k)]);
        }
    }

    float* o = out + (blockIdx.x * 16 + wl) * 80;
#pragma unroll
    for (int i = 0; i < 5; ++i)
        o[i * 16 + f] = __half2float(mx[i]) + bias[i];
}

// ---------------------------------------------------------------------------
extern "C" void kernel_launch(void* const* d_in, const int* in_sizes, int n_in,
                              void* d_out, int out_size)
{
    const int*   word = (const int*)  d_in[0];
    const float* emb  = (const float*)d_in[1];
    const float* w2   = (const float*)d_in[2];
    const float* b2   = (const float*)d_in[3];
    const float* w3   = (const float*)d_in[4];
    const float* b3   = (const float*)d_in[5];
    const float* w4   = (const float*)d_in[6];
    const float* b4   = (const float*)d_in[7];
    const float* w5   = (const float*)d_in[8];
    const float* b5   = (const float*)d_in[9];
    const float* w6   = (const float*)d_in[10];
    const float* b6   = (const float*)d_in[11];
    float* out = (float*)d_out;

    build_table<<<VOC / VT, 320>>>(emb, w2, w3, w4, w5, w6);
    cnn_max<<<1024, 256>>>(word, b2, b3, b4, b5, b6, out);
}